// round 10
// baseline (speedup 1.0000x reference)
#include <cuda_runtime.h>
#include <math_constants.h>

// Derived from the reference:
//   t = arange(-401//2, 401//2 + 1) = arange(-201, 201) -> 402 taps
//   L_out = 16000 - 402 + 1 = 15599
// Harness evidence (R8/R9): output buffer is float32 with
// out_size = 16*64*15599 = 15,973,376 elements = the REAL part only.
#define NFILT   64
#define KTAPS   402
#define T0      (-201)
#define BATCH   16
#define L_IN    16000
#define L_OUT   (L_IN - KTAPS + 1)      // 15599
#define L_TOTAL ((long long)BATCH * NFILT * L_OUT)   // 15,973,376

#define THREADS  256
#define TILE_O   1024                    // 4 outputs per thread
#define SXL      (TILE_O + KTAPS + 2)    // 1428
#define NTILES   ((L_OUT + TILE_O - 1) / TILE_O)   // 16

// WRITE_IMAG=0: real-only output (primary, per H-B evidence).
// WRITE_IMAG=1: planar [re_all | im_all] fallback (if out_size >= 2*L_TOTAL).
template <int WRITE_IMAG>
__global__ void gabor_kernel(const float* x, int n_x,
                             const float* p0, const float* p1, int n_p,
                             float* outf, long long cap_floats) {
    __shared__ float sx[SXL];
    __shared__ float sfr[KTAPS];
    __shared__ float sfi[KTAPS];

    const int bid  = blockIdx.x;
    const int tile = bid % NTILES;
    const int f    = (bid / NTILES) % NFILT;
    const int b    = bid / (NTILES * NFILT);
    const int o0   = tile * TILE_O;
    const int tid  = threadIdx.x;

    // Build this filter's taps (cf in [0.1,3], bw in [10,100]: disjoint ranges,
    // so min = center frequency, max = bandwidth, order-agnostic).
    {
        float v0 = (f < n_p) ? p0[f] : 1.0f;
        float v1 = (f < n_p) ? p1[f] : 50.0f;
        float c  = fminf(v0, v1);
        float bw = fmaxf(v0, v1);
        float inv2b2 = 1.0f / (2.0f * bw * bw);
        float norm   = 1.0f / (sqrtf(2.0f * CUDART_PI_F) * bw);
        for (int k = tid; k < KTAPS; k += THREADS) {
            float t = (float)(k + T0);
            float env = expf(-t * t * inv2b2) * norm;
            float s, co;
            sincosf(c * t, &s, &co);
            sfr[k] = env * co;
            if (WRITE_IMAG) sfi[k] = env * s;
        }
    }

    // Load x tile, fully guarded, scalar.
    {
        long long xbase = (long long)b * (long long)L_IN;
        for (int i = tid; i < SXL; i += THREADS) {
            int gi = o0 + i;
            float v = 0.0f;
            if (gi < L_IN) {
                long long gidx = xbase + (long long)gi;
                if (gidx < (long long)n_x) v = x[gidx];
            }
            sx[i] = v;
        }
    }
    __syncthreads();

    const int base = tid * 4;   // first output (within tile) for this thread

    float ar[4] = {0.f, 0.f, 0.f, 0.f};
    float ai[4] = {0.f, 0.f, 0.f, 0.f};

    // Main taps k = 0..399 in blocks of 4.
    // Max sx index: base(1020) + kb(396) + t(6) = 1422 < 1428.
    for (int kb = 0; kb < KTAPS - 2; kb += 4) {
        float xv[7];
        #pragma unroll
        for (int t = 0; t < 7; t++) xv[t] = sx[base + kb + t];

        #pragma unroll
        for (int dk = 0; dk < 4; dk++) {
            float wr = sfr[kb + dk];
            #pragma unroll
            for (int j = 0; j < 4; j++)
                ar[j] = fmaf(xv[dk + j], wr, ar[j]);
            if (WRITE_IMAG) {
                float wi = sfi[kb + dk];
                #pragma unroll
                for (int j = 0; j < 4; j++)
                    ai[j] = fmaf(xv[dk + j], wi, ai[j]);
            }
        }
    }

    // Tail taps k = 400, 401. Max sx index: 1020 + 400 + 4 = 1424 < 1428.
    {
        float xv[5];
        #pragma unroll
        for (int t = 0; t < 5; t++) xv[t] = sx[base + (KTAPS - 2) + t];
        #pragma unroll
        for (int dk = 0; dk < 2; dk++) {
            float wr = sfr[(KTAPS - 2) + dk];
            #pragma unroll
            for (int j = 0; j < 4; j++)
                ar[j] = fmaf(xv[dk + j], wr, ar[j]);
            if (WRITE_IMAG) {
                float wi = sfi[(KTAPS - 2) + dk];
                #pragma unroll
                for (int j = 0; j < 4; j++)
                    ai[j] = fmaf(xv[dk + j], wi, ai[j]);
            }
        }
    }

    // Store. Real-only: one float per output, guarded by cap_floats.
    // Planar fallback: real plane [0,H), imag plane [H,2H), H = cap/2.
    long long row = (long long)(b * NFILT + f) * (long long)L_OUT;
    const long long H = cap_floats / 2;
    #pragma unroll
    for (int j = 0; j < 4; j++) {
        int o = o0 + base + j;
        if (o < L_OUT) {
            long long lin = row + (long long)o;
            if (!WRITE_IMAG) {
                if (lin < cap_floats) outf[lin] = ar[j];
            } else {
                if (lin < H)              outf[lin]     = ar[j];
                if (H + lin < cap_floats) outf[H + lin] = ai[j];
            }
        }
    }
}

extern "C" void kernel_launch(void* const* d_in, const int* in_sizes, int n_in,
                              void* d_out, int out_size) {
    // Identify inputs by size (order-agnostic): x = largest buffer; the two
    // remaining buffers are cf/bw, disambiguated by value range in-kernel.
    int xi = -1;
    for (int i = 0; i < n_in; i++) {
        if (xi < 0 || in_sizes[i] > in_sizes[xi]) xi = i;
    }
    if (xi < 0) return;
    const float* x = (const float*)d_in[xi];
    int n_x = in_sizes[xi];

    const float* pa = nullptr; int na = 0;
    const float* pb = nullptr; int nb = 0;
    for (int i = 0; i < n_in; i++) {
        if (i == xi) continue;
        if (!pa)      { pa = (const float*)d_in[i]; na = in_sizes[i]; }
        else if (!pb) { pb = (const float*)d_in[i]; nb = in_sizes[i]; }
    }
    if (!x || !pa || !pb) return;
    int n_p = (na < nb) ? na : nb;

    int nblocks = NTILES * NFILT * BATCH;   // 16 * 64 * 16 = 16384
    if ((long long)out_size >= 2 * L_TOTAL) {
        // Planar complex fallback (H-A).
        gabor_kernel<1><<<nblocks, THREADS>>>(x, n_x, pa, pb, n_p,
                                              (float*)d_out, (long long)out_size);
    } else {
        // Real-part-only output (H-B, primary).
        gabor_kernel<0><<<nblocks, THREADS>>>(x, n_x, pa, pb, n_p,
                                              (float*)d_out, (long long)out_size);
    }
}

// round 11
// speedup vs baseline: 4.2085x; 4.2085x over previous
#include <cuda_runtime.h>
#include <math_constants.h>

// Derived from the reference:
//   t = arange(-401//2, 401//2 + 1) = arange(-201, 201) -> 402 taps
//   L_out = 16000 - 402 + 1 = 15599
// Harness evidence (R8-R10): output is float32, out_size = 16*64*15599 =
// 15,973,376 elements = the REAL part of the complex result only.
#define NFILT   64
#define KTAPS   402
#define T0      (-201)
#define BATCH   16
#define L_IN    16000
#define L_OUT   (L_IN - KTAPS + 1)      // 15599

#define THREADS  256
#define TILE_O   1024                    // 4 consecutive outputs per thread
#define SXL      1428                    // >= TILE_O+KTAPS-1 (1425), /4 = 357
#define NTILES   ((L_OUT + TILE_O - 1) / TILE_O)   // 16
#define FPC      4                       // filters per CTA
#define NFGRP    (NFILT / FPC)           // 16
#define SFROW    404                     // KTAPS padded to multiple of 4

// Precomputed REAL filter bank (env * cos(c*t)), 64*402*4B = 103 KB scratch.
__device__ float g_filt[NFILT][SFROW];

__global__ void build_filters_kernel(const float* __restrict__ p0,
                                     const float* __restrict__ p1, int n_p) {
    int f = blockIdx.x;
    if (f >= NFILT) return;
    // cf in [0.1, 3.0], bw in [10, 100]: disjoint ranges -> min = cf, max = bw.
    float v0 = (f < n_p) ? p0[f] : 1.0f;
    float v1 = (f < n_p) ? p1[f] : 50.0f;
    float c  = fminf(v0, v1);
    float bw = fmaxf(v0, v1);
    float inv2b2 = 1.0f / (2.0f * bw * bw);
    float norm   = 1.0f / (sqrtf(2.0f * CUDART_PI_F) * bw);
    for (int k = threadIdx.x; k < SFROW; k += blockDim.x) {
        float val = 0.0f;
        if (k < KTAPS) {
            float t = (float)(k + T0);
            float env = expf(-t * t * inv2b2) * norm;
            val = env * __cosf(0.0f) * 0.0f + env * cosf(c * t); // plain cosf
        }
        g_filt[f][k] = val;
    }
}

__global__ __launch_bounds__(THREADS)
void gabor_conv_kernel(const float* __restrict__ x, int n_x,
                       float* __restrict__ outf, long long cap_floats) {
    __shared__ __align__(16) float sx[SXL];
    __shared__ __align__(16) float sf[FPC][SFROW];

    const int bid  = blockIdx.x;
    const int tile = bid % NTILES;
    const int fg   = (bid / NTILES) % NFGRP;
    const int b    = bid / (NTILES * NFGRP);
    const int o0   = tile * TILE_O;
    const int f0   = fg * FPC;
    const int tid  = threadIdx.x;

    // Load x tile (guarded, scalar, coalesced).
    {
        long long xbase = (long long)b * (long long)L_IN;
        for (int i = tid; i < SXL; i += THREADS) {
            int gi = o0 + i;
            float v = 0.0f;
            if (gi < L_IN) {
                long long gidx = xbase + (long long)gi;
                if (gidx < (long long)n_x) v = x[gidx];
            }
            sx[i] = v;
        }
    }
    // Load the 4 filters' taps from the precomputed bank.
    for (int i = tid; i < FPC * SFROW; i += THREADS) {
        int fi = i / SFROW;
        int k  = i % SFROW;
        sf[fi][k] = g_filt[f0 + fi][k];
    }
    __syncthreads();

    const int base = tid * 4;                 // outputs o0+base .. o0+base+3
    const float4* sx4 = (const float4*)sx;    // conflict-free LDS.128

    float acc[FPC][4];
    #pragma unroll
    for (int fi = 0; fi < FPC; fi++)
        #pragma unroll
        for (int j = 0; j < 4; j++) acc[fi][j] = 0.0f;

    // 8-float sliding register window over x.
    float xw0, xw1, xw2, xw3, xw4, xw5, xw6, xw7;
    {
        float4 v = sx4[tid];
        xw0 = v.x; xw1 = v.y; xw2 = v.z; xw3 = v.w;
    }

    // Main taps 0..399: 100 blocks of 4 taps.
    // Per block: 1 LDS.128 (x) + FPC LDS.128 broadcasts (filters) + 64 FMA.
    #pragma unroll 2
    for (int kq = 0; kq < (KTAPS - 2) / 4; kq++) {
        float4 nv = sx4[tid + kq + 1];        // max index 255+100 = 355 < 357
        xw4 = nv.x; xw5 = nv.y; xw6 = nv.z; xw7 = nv.w;

        #pragma unroll
        for (int fi = 0; fi < FPC; fi++) {
            float4 w = ((const float4*)sf[fi])[kq];   // taps 4kq .. 4kq+3
            acc[fi][0] = fmaf(xw0, w.x, acc[fi][0]);
            acc[fi][1] = fmaf(xw1, w.x, acc[fi][1]);
            acc[fi][2] = fmaf(xw2, w.x, acc[fi][2]);
            acc[fi][3] = fmaf(xw3, w.x, acc[fi][3]);

            acc[fi][0] = fmaf(xw1, w.y, acc[fi][0]);
            acc[fi][1] = fmaf(xw2, w.y, acc[fi][1]);
            acc[fi][2] = fmaf(xw3, w.y, acc[fi][2]);
            acc[fi][3] = fmaf(xw4, w.y, acc[fi][3]);

            acc[fi][0] = fmaf(xw2, w.z, acc[fi][0]);
            acc[fi][1] = fmaf(xw3, w.z, acc[fi][1]);
            acc[fi][2] = fmaf(xw4, w.z, acc[fi][2]);
            acc[fi][3] = fmaf(xw5, w.z, acc[fi][3]);

            acc[fi][0] = fmaf(xw3, w.w, acc[fi][0]);
            acc[fi][1] = fmaf(xw4, w.w, acc[fi][1]);
            acc[fi][2] = fmaf(xw5, w.w, acc[fi][2]);
            acc[fi][3] = fmaf(xw6, w.w, acc[fi][3]);
        }
        xw0 = xw4; xw1 = xw5; xw2 = xw6; xw3 = xw7;
    }

    // Tail taps k = 400, 401 (scalar; max sx index 1020+401+3 = 1424 < 1428).
    {
        float xv[5];
        #pragma unroll
        for (int t = 0; t < 5; t++) xv[t] = sx[base + (KTAPS - 2) + t];
        #pragma unroll
        for (int dk = 0; dk < 2; dk++) {
            #pragma unroll
            for (int fi = 0; fi < FPC; fi++) {
                float w = sf[fi][(KTAPS - 2) + dk];
                #pragma unroll
                for (int j = 0; j < 4; j++)
                    acc[fi][j] = fmaf(xv[dk + j], w, acc[fi][j]);
            }
        }
    }

    // Store real outputs, guarded by logical length and physical capacity.
    #pragma unroll
    for (int fi = 0; fi < FPC; fi++) {
        long long row = (long long)(b * NFILT + (f0 + fi)) * (long long)L_OUT;
        #pragma unroll
        for (int j = 0; j < 4; j++) {
            int o = o0 + base + j;
            if (o < L_OUT) {
                long long lin = row + (long long)o;
                if (lin < cap_floats) outf[lin] = acc[fi][j];
            }
        }
    }
}

extern "C" void kernel_launch(void* const* d_in, const int* in_sizes, int n_in,
                              void* d_out, int out_size) {
    // Identify inputs by size (order-agnostic): x = largest buffer; the two
    // remaining buffers are cf/bw, disambiguated by value range in-kernel.
    int xi = -1;
    for (int i = 0; i < n_in; i++) {
        if (xi < 0 || in_sizes[i] > in_sizes[xi]) xi = i;
    }
    if (xi < 0) return;
    const float* x = (const float*)d_in[xi];
    int n_x = in_sizes[xi];

    const float* pa = nullptr; int na = 0;
    const float* pb = nullptr; int nb = 0;
    for (int i = 0; i < n_in; i++) {
        if (i == xi) continue;
        if (!pa)      { pa = (const float*)d_in[i]; na = in_sizes[i]; }
        else if (!pb) { pb = (const float*)d_in[i]; nb = in_sizes[i]; }
    }
    if (!x || !pa || !pb) return;
    int n_p = (na < nb) ? na : nb;

    build_filters_kernel<<<NFILT, 128>>>(pa, pb, n_p);

    int nblocks = NTILES * NFGRP * BATCH;   // 16 * 16 * 16 = 4096
    gabor_conv_kernel<<<nblocks, THREADS>>>(x, n_x,
                                            (float*)d_out, (long long)out_size);
}